// round 8
// baseline (speedup 1.0000x reference)
#include <cuda_runtime.h>
#include <cuda_bf16.h>
#include <math.h>
#include <stdint.h>

#define OUTW 7
#define SPP 4
#define CCH 256
#define HH 128
#define WW 128
#define BB 4
#define NROI 2000
#define FIN (OUTW*OUTW*CCH)   /* 12544 */
#define FC 1024
#define NBIN (OUTW*OUTW)      /* 49 */
#define KP1 (FIN/2)           /* 6272 */
#define KP2 (FC/2)            /* 512 */

// ---------------- scratch (static device globals; no dynamic alloc) ----------
__device__ float          g_dataT[(size_t)BB*HH*WW*CCH];   // [B,H,W,C] 64 MB
__device__ __nv_bfloat16  g_xf[(size_t)NROI*FIN];          // pooled feats bf16
__device__ __nv_bfloat16  g_h1[(size_t)NROI*FC];
__device__ __nv_bfloat16  g_m1[(size_t)NROI*FC];
__device__ __nv_bfloat16  g_h2[(size_t)NROI*FC];
__device__ float          g_off[(size_t)NROI*2*NBIN];
__device__ float          g_mask[(size_t)NROI*NBIN];
__device__ uint32_t       g_w1p[(size_t)FC*KP1];           // [n][kp] bf16x2, permuted k
__device__ uint32_t       g_mw1p[(size_t)FC*KP1];
__device__ uint32_t       g_w2p[(size_t)FC*KP2];           // [n][kp]

// ---------------- helpers ------------------------------------------------------
__device__ __forceinline__ uint32_t packbf(float lo, float hi) {
    __nv_bfloat162 h = __floats2bfloat162_rn(lo, hi);
    return *(uint32_t*)&h;
}

__device__ __forceinline__ void mma_bf16(float* c, const uint32_t* a, const uint32_t* b) {
    asm volatile(
        "mma.sync.aligned.m16n8k16.row.col.f32.bf16.bf16.f32 "
        "{%0,%1,%2,%3}, {%4,%5,%6,%7}, {%8,%9}, {%0,%1,%2,%3};"
        : "+f"(c[0]), "+f"(c[1]), "+f"(c[2]), "+f"(c[3])
        : "r"(a[0]), "r"(a[1]), "r"(a[2]), "r"(a[3]), "r"(b[0]), "r"(b[1]));
}

__device__ __forceinline__ void ldsm_x4(uint32_t& r0, uint32_t& r1,
                                        uint32_t& r2, uint32_t& r3, uint32_t addr) {
    asm volatile("ldmatrix.sync.aligned.m8n8.x4.shared.b16 {%0,%1,%2,%3}, [%4];"
                 : "=r"(r0), "=r"(r1), "=r"(r2), "=r"(r3) : "r"(addr));
}

__device__ __forceinline__ void cp_async16(uint32_t dst, const void* src, bool pred) {
    int sz = pred ? 16 : 0;
    asm volatile("cp.async.cg.shared.global [%0], [%1], 16, %2;\n"
                 :: "r"(dst), "l"(src), "r"(sz));
}
__device__ __forceinline__ void cp_commit() {
    asm volatile("cp.async.commit_group;\n" ::: "memory");
}
template <int N>
__device__ __forceinline__ void cp_wait() {
    asm volatile("cp.async.wait_group %0;\n" :: "n"(N) : "memory");
}

// ---------------- transpose [B,C,H,W] -> [B,H,W,C] ---------------------------
__global__ void k_transpose(const float* __restrict__ data) {
    __shared__ float tile[32][33];
    int xt = blockIdx.x;
    int by = blockIdx.y;
    int ct = blockIdx.z;
    int b = by >> 7, y = by & 127;
    int x0 = xt * 32, c0 = ct * 32;
    int tx = threadIdx.x, ty = threadIdx.y;
#pragma unroll
    for (int i = 0; i < 4; i++) {
        int c = c0 + ty + 8 * i;
        tile[ty + 8 * i][tx] =
            data[(((size_t)b * CCH + c) * HH + y) * WW + x0 + tx];
    }
    __syncthreads();
#pragma unroll
    for (int i = 0; i < 4; i++) {
        int x = x0 + ty + 8 * i;
        g_dataT[(((size_t)b * HH + y) * WW + x) * CCH + c0 + tx] =
            tile[tx][ty + 8 * i];
    }
}

// ---------------- weight prep: w1/mw1 -> [n][kp] bf16x2, permuted k ----------
// permuted k = bin*256+c  (source row c*49+bin). 64 k x 32 n tile per block.
__global__ void k_wprep(const float* __restrict__ w1, const float* __restrict__ mw1) {
    __shared__ float t[64][33];
    int kk0 = blockIdx.x * 64;
    int n0 = blockIdx.y * 32;
    int tx = threadIdx.x, ty = threadIdx.y;   // 32 x 8

    // ---- w1 ----
#pragma unroll
    for (int i = 0; i < 8; i++) {
        int gk = kk0 + ty + 8 * i;
        int c = gk & 255, bin = gk >> 8;
        t[ty + 8 * i][tx] = w1[(size_t)(c * NBIN + bin) * FC + n0 + tx];
    }
    __syncthreads();
#pragma unroll
    for (int i = 0; i < 4; i++) {
        int ny = ty + 8 * i;
        g_w1p[(size_t)(n0 + ny) * KP1 + (kk0 >> 1) + tx] =
            packbf(t[2 * tx][ny], t[2 * tx + 1][ny]);
    }
    __syncthreads();

    // ---- mw1 ----
#pragma unroll
    for (int i = 0; i < 8; i++) {
        int gk = kk0 + ty + 8 * i;
        int c = gk & 255, bin = gk >> 8;
        t[ty + 8 * i][tx] = mw1[(size_t)(c * NBIN + bin) * FC + n0 + tx];
    }
    __syncthreads();
#pragma unroll
    for (int i = 0; i < 4; i++) {
        int ny = ty + 8 * i;
        g_mw1p[(size_t)(n0 + ny) * KP1 + (kk0 >> 1) + tx] =
            packbf(t[2 * tx][ny], t[2 * tx + 1][ny]);
    }
}

__global__ void k_w2prep(const float* __restrict__ w2) {
    __shared__ float t[64][33];
    int kk0 = blockIdx.x * 64;
    int n0 = blockIdx.y * 32;
    int tx = threadIdx.x, ty = threadIdx.y;
#pragma unroll
    for (int i = 0; i < 8; i++)
        t[ty + 8 * i][tx] = w2[(size_t)(kk0 + ty + 8 * i) * FC + n0 + tx];
    __syncthreads();
#pragma unroll
    for (int i = 0; i < 4; i++) {
        int ny = ty + 8 * i;
        g_w2p[(size_t)(n0 + ny) * KP2 + (kk0 >> 1) + tx] =
            packbf(t[2 * tx][ny], t[2 * tx + 1][ny]);
    }
}

// ---------------- deform ROI pool: per-cell weight factorization --------------
__global__ void __launch_bounds__(64) k_pool(
        const float* __restrict__ rois,
        const float* __restrict__ offset,
        const float* __restrict__ mask,
        float* __restrict__ outf,
        __nv_bfloat16* __restrict__ outh,
        int pass) {
    int bidx = blockIdx.x;
    int n = bidx / NBIN;
    int bin = bidx % NBIN;
    int ph = bin / OUTW, pw = bin % OUTW;
    int tid = threadIdx.x;

    __shared__ float wcell[48];
    __shared__ float snorm;
    __shared__ int   sbase;
    __shared__ unsigned long long smask;

    if (tid < 48) wcell[tid] = 0.0f;
    __syncthreads();

    const float* r = rois + n * 5;
    if (tid < 16) {
        float sw = floorf(r[1] + 0.5f) * 0.0625f - 0.5f;
        float sh = floorf(r[2] + 0.5f) * 0.0625f - 0.5f;
        float ew = (floorf(r[3] + 0.5f) + 1.0f) * 0.0625f - 0.5f;
        float eh = (floorf(r[4] + 0.5f) + 1.0f) * 0.0625f - 0.5f;
        float rw = fmaxf(ew - sw, 0.1f);
        float rh = fmaxf(eh - sh, 0.1f);
        float bw = rw / 7.0f, bh = rh / 7.0f;
        float subw = bw / 4.0f, subh = bh / 4.0f;
        float ws0 = (float)pw * bw + sw;
        float hs0 = (float)ph * bh + sh;
        if (pass == 2) {
            ws0 += offset[(size_t)n * 98 + bin] * 0.1f * rw;
            hs0 += offset[(size_t)n * 98 + 49 + bin] * 0.1f * rh;
        }
        int ix = tid & 3, iy = tid >> 2;
        float w = ws0 + (float)ix * subw;
        float h = hs0 + (float)iy * subh;
        bool valid = (w >= -0.5f) && (w <= (float)WW - 0.5f) &&
                     (h >= -0.5f) && (h <= (float)HH - 0.5f);
        float wc = fminf(fmaxf(w, 0.0f), (float)(WW - 1));
        float hc = fminf(fmaxf(h, 0.0f), (float)(HH - 1));
        int x0 = (int)floorf(wc);
        int y0 = (int)floorf(hc);
        int x1 = min(x0 + 1, WW - 1);
        int y1 = min(y0 + 1, HH - 1);
        int gx = x0, gy = y0;
#pragma unroll
        for (int o = 8; o >= 1; o >>= 1) {
            gx = min(gx, __shfl_xor_sync(0xFFFFu, gx, o));
            gy = min(gy, __shfl_xor_sync(0xFFFFu, gy, o));
        }
        float dx = wc - (float)x0;
        float dy = hc - (float)y0;
        int c00 = ((y0 - gy) << 3) + (x0 - gx);
        int c01 = ((y0 - gy) << 3) + (x1 - gx);
        int c10 = ((y1 - gy) << 3) + (x0 - gx);
        int c11 = ((y1 - gy) << 3) + (x1 - gx);
        unsigned long long m = 0ull;
        float cnt = valid ? 1.0f : 0.0f;
        if (valid) {
            atomicAdd(&wcell[c00], (1.0f - dx) * (1.0f - dy));
            atomicAdd(&wcell[c01], dx * (1.0f - dy));
            atomicAdd(&wcell[c10], (1.0f - dx) * dy);
            atomicAdd(&wcell[c11], dx * dy);
            m = (1ull << c00) | (1ull << c01) | (1ull << c10) | (1ull << c11);
        }
#pragma unroll
        for (int o = 8; o >= 1; o >>= 1) {
            m |= __shfl_xor_sync(0xFFFFu, m, o);
            cnt += __shfl_xor_sync(0xFFFFu, cnt, o);
        }
        if (tid == 0) {
            smask = m;
            int b = (int)r[0];
            sbase = b * (HH * WW * 64) + (gy * WW + gx) * 64;  // float4 units
            float norm = (cnt > 0.0f) ? 1.0f / cnt : 0.0f;
            if (pass == 2) norm *= mask[(size_t)n * NBIN + bin];
            snorm = norm;
        }
    }
    __syncthreads();

    unsigned long long m = smask;
    float norm = snorm;
    const float4* base = (const float4*)g_dataT;
    int baseIdx = sbase + tid;

    float ax = 0.f, ay = 0.f, az = 0.f, aw = 0.f;
    while (m) {
        int cell = __ffsll((long long)m) - 1;
        m &= m - 1;
        float w = wcell[cell];
        int idx = baseIdx + (cell >> 3) * (WW * 64) + (cell & 7) * 64;
        float4 v = base[idx];
        ax += w * v.x; ay += w * v.y; az += w * v.z; aw += w * v.w;
    }
    ax *= norm; ay *= norm; az *= norm; aw *= norm;

    if (pass == 2) {
        float* o = outf + (size_t)n * FIN + (size_t)(tid * 4) * NBIN + bin;
        o[0]        = ax;
        o[NBIN]     = ay;
        o[2 * NBIN] = az;
        o[3 * NBIN] = aw;
    } else {
        uint2 v = make_uint2(packbf(ax, ay), packbf(az, aw));
        *(uint2*)(outh + (size_t)n * FIN + (size_t)bin * 256 + tid * 4) = v;
    }
}

// ---------------- bf16 tensor-core GEMM (4-stage cp.async + ldmatrix) ---------
// A [M,K] bf16 row-major (lda elems). B n-major u32 [N][K/2].
// C bf16 [M,ldc]. K%32==0, N%128==0. gridDim.z==2 selects second head.
#define LDA_S 20    /* u32 per A smem row (16 used) */
#define LDB_S 20    /* u32 per B smem n-row (16 used) */
#define STAGES 4
#define A_ST (128 * LDA_S)
#define B_ST (128 * LDB_S)
#define GEMM_SMEM ((STAGES * (A_ST + B_ST)) * 4)

__global__ void __launch_bounds__(256, 2) k_gemm_bf16(
    const __nv_bfloat16* __restrict__ A, int lda,
    const uint32_t* __restrict__ B,
    const float* __restrict__ bias,
    __nv_bfloat16* __restrict__ C, int ldc,
    const uint32_t* __restrict__ B2,
    const float* __restrict__ bias2,
    __nv_bfloat16* __restrict__ C2,
    int M, int K, int act) {
    if (blockIdx.z == 1) { B = B2; bias = bias2; C = C2; }
    int Kp = K >> 1;

    extern __shared__ uint32_t sm[];
    uint32_t* Asm = sm;                       // STAGES * A_ST
    uint32_t* Bsm = sm + STAGES * A_ST;       // STAGES * B_ST

    int tid = threadIdx.x;
    int warp = tid >> 5, lane = tid & 31;
    int wm = warp >> 2;
    int wn = warp & 3;
    int bm = blockIdx.y * 128, bn = blockIdx.x * 128;

    // A global load mapping (rows 0..63 and 64..127, 16B chunks of kpairs)
    int arow = tid >> 2;              // 0..63
    int akc  = (tid & 3) * 4;         // u32 pair offset 0,4,8,12
    const __nv_bfloat16* Ap0 = A + (size_t)(bm + arow) * lda + akc * 2;
    const __nv_bfloat16* Ap1 = A + (size_t)(bm + arow + 64) * lda + akc * 2;
    bool am0 = (bm + arow) < M;
    bool am1 = (bm + arow + 64) < M;

    // B global load mapping: n rows 0..63 / 64..127, 16B chunks along kp
    int brow = tid >> 2;              // 0..63
    int bkc  = (tid & 3) * 4;         // u32 col 0,4,8,12
    const uint32_t* Bq0 = B + (size_t)(bn + brow) * Kp + bkc;
    const uint32_t* Bq1 = B + (size_t)(bn + brow + 64) * Kp + bkc;

    uint32_t a_smem = (uint32_t)__cvta_generic_to_shared(Asm);
    uint32_t b_smem = (uint32_t)__cvta_generic_to_shared(Bsm);
    uint32_t da0 = a_smem + (uint32_t)(arow * LDA_S + akc) * 4;
    uint32_t da1 = a_smem + (uint32_t)((arow + 64) * LDA_S + akc) * 4;
    uint32_t db0 = b_smem + (uint32_t)(brow * LDB_S + bkc) * 4;
    uint32_t db1 = b_smem + (uint32_t)((brow + 64) * LDB_S + bkc) * 4;

    // ldmatrix per-lane bases
    uint32_t a_lm = a_smem +
        (uint32_t)(((wm * 64 + (lane & 15)) * LDA_S) + ((lane >> 4) << 2)) * 4;
    uint32_t b_lm = b_smem +
        (uint32_t)(((wn * 32 + (lane & 7) + ((lane >> 4) << 3)) * LDB_S)
                   + (((lane >> 3) & 1) << 2)) * 4;

    float acc[4][4][4];
#pragma unroll
    for (int i = 0; i < 4; i++)
#pragma unroll
        for (int j = 0; j < 4; j++)
#pragma unroll
            for (int q = 0; q < 4; q++) acc[i][j][q] = 0.0f;

    int nt = K / 32;

#define LOAD_STAGE(kt, s)                                                      \
    {                                                                          \
        int ke = (kt) * 32;                                                    \
        int kp = (kt) * 16;                                                    \
        uint32_t ao = (uint32_t)(s) * A_ST * 4;                                \
        uint32_t bo = (uint32_t)(s) * B_ST * 4;                                \
        cp_async16(da0 + ao, Ap0 + ke, am0);                                   \
        cp_async16(da1 + ao, Ap1 + ke, am1);                                   \
        cp_async16(db0 + bo, Bq0 + kp, true);                                  \
        cp_async16(db1 + bo, Bq1 + kp, true);                                  \
        cp_commit();                                                           \
    }

    LOAD_STAGE(0, 0);
    LOAD_STAGE(1, 1);
    LOAD_STAGE(2, 2);

    for (int kt = 0; kt < nt; kt++) {
        cp_wait<STAGES - 2>();
        __syncthreads();
        if (kt + 3 < nt) {
            LOAD_STAGE(kt + 3, (kt + 3) & 3);
        } else {
            cp_commit();            // keep group counting uniform
        }

        int cur = kt & 3;
        uint32_t ab = a_lm + (uint32_t)cur * A_ST * 4;
        uint32_t bb = b_lm + (uint32_t)cur * B_ST * 4;

        uint32_t af[2][4][4], bf[2][4][2];
#pragma unroll
        for (int ko = 0; ko < 2; ko++) {
#pragma unroll
            for (int i = 0; i < 4; i++)
                ldsm_x4(af[ko][i][0], af[ko][i][1], af[ko][i][2], af[ko][i][3],
                        ab + (uint32_t)(i * 16 * LDA_S * 4 + ko * 32));
#pragma unroll
            for (int jj = 0; jj < 2; jj++)
                ldsm_x4(bf[ko][2 * jj][0], bf[ko][2 * jj][1],
                        bf[ko][2 * jj + 1][0], bf[ko][2 * jj + 1][1],
                        bb + (uint32_t)(jj * 16 * LDB_S * 4 + ko * 32));
        }
#pragma unroll
        for (int ko = 0; ko < 2; ko++)
#pragma unroll
            for (int i = 0; i < 4; i++)
#pragma unroll
                for (int j = 0; j < 4; j++)
                    mma_bf16(acc[i][j], af[ko][i], bf[ko][j]);
        __syncthreads();
    }
    cp_wait<0>();

    // epilogue: bias + act, store bf16 pairs
    int g = lane >> 2, t = lane & 3;
#pragma unroll
    for (int i = 0; i < 4; i++) {
        int r0 = bm + wm * 64 + i * 16 + g;
        int r1 = r0 + 8;
#pragma unroll
        for (int j = 0; j < 4; j++) {
            int c0 = bn + wn * 32 + j * 8 + 2 * t;
            float bv0 = bias[c0], bv1 = bias[c0 + 1];
            float vv[4] = {acc[i][j][0] + bv0, acc[i][j][1] + bv1,
                           acc[i][j][2] + bv0, acc[i][j][3] + bv1};
#pragma unroll
            for (int q = 0; q < 4; q++) {
                if (act == 1) vv[q] = fmaxf(vv[q], 0.0f);
                else if (act == 2) vv[q] = 1.0f / (1.0f + expf(-vv[q]));
            }
            if (r0 < M)
                *(uint32_t*)(C + (size_t)r0 * ldc + c0) = packbf(vv[0], vv[1]);
            if (r1 < M)
                *(uint32_t*)(C + (size_t)r1 * ldc + c0) = packbf(vv[2], vv[3]);
        }
    }
#undef LOAD_STAGE
}

// ---------------- small-N head GEMM (A bf16, B/bias fp32) ---------------------
__global__ void __launch_bounds__(256) k_head(
        const __nv_bfloat16* __restrict__ A, const float* __restrict__ B,
        const float* __restrict__ bias, float* __restrict__ C,
        int N, int act) {
    __shared__ float Asm[8 * FC];
    int tid = threadIdx.x;
    int m0 = blockIdx.x * 8;
    const uint4* Af = (const uint4*)(A + (size_t)m0 * FC);  // 8 bf16 per uint4
#pragma unroll
    for (int i = 0; i < 4; i++) {
        int idx = tid + 256 * i;            // 1024 uint4 total
        uint4 u = Af[idx];
        float2 f0 = __bfloat1622float2(*(__nv_bfloat162*)&u.x);
        float2 f1 = __bfloat1622float2(*(__nv_bfloat162*)&u.y);
        float2 f2 = __bfloat1622float2(*(__nv_bfloat162*)&u.z);
        float2 f3 = __bfloat1622float2(*(__nv_bfloat162*)&u.w);
        float* d = Asm + idx * 8;
        d[0] = f0.x; d[1] = f0.y; d[2] = f1.x; d[3] = f1.y;
        d[4] = f2.x; d[5] = f2.y; d[6] = f3.x; d[7] = f3.y;
    }
    __syncthreads();

    int row = tid >> 5, lane = tid & 31;
    float acc[4] = {0.f, 0.f, 0.f, 0.f};
    const float* ar = Asm + row * FC;
    for (int k = 0; k < FC; k += 2) {
        float a0 = ar[k], a1 = ar[k + 1];
        const float* bk0 = B + (size_t)k * N;
        const float* bk1 = bk0 + N;
#pragma unroll
        for (int j = 0; j < 4; j++) {
            int col = lane + 32 * j;
            if (col < N) {
                acc[j] += a0 * bk0[col];
                acc[j] += a1 * bk1[col];
            }
        }
    }
#pragma unroll
    for (int j = 0; j < 4; j++) {
        int col = lane + 32 * j;
        if (col < N) {
            float v = acc[j] + bias[col];
            if (act == 1) v = fmaxf(v, 0.0f);
            else if (act == 2) v = 1.0f / (1.0f + expf(-v));
            C[(size_t)(m0 + row) * N + col] = v;
        }
    }
}

// ---------------- launch ------------------------------------------------------
extern "C" void kernel_launch(void* const* d_in, const int* in_sizes, int n_in,
                              void* d_out, int out_size) {
    const float* data = (const float*)d_in[0];
    const float* rois = (const float*)d_in[1];
    const float* w1   = (const float*)d_in[2];
    const float* b1   = (const float*)d_in[3];
    const float* w2   = (const float*)d_in[4];
    const float* b2   = (const float*)d_in[5];
    const float* w3   = (const float*)d_in[6];
    const float* b3   = (const float*)d_in[7];
    const float* mw1  = (const float*)d_in[8];
    const float* mb1  = (const float*)d_in[9];
    const float* mw2  = (const float*)d_in[10];
    const float* mb2  = (const float*)d_in[11];
    float* out = (float*)d_out;

    __nv_bfloat16 *xf, *h1, *m1, *h2;
    float *off, *maskb;
    uint32_t *w1p, *mw1p, *w2p;
    cudaGetSymbolAddress((void**)&xf,    g_xf);
    cudaGetSymbolAddress((void**)&h1,    g_h1);
    cudaGetSymbolAddress((void**)&m1,    g_m1);
    cudaGetSymbolAddress((void**)&h2,    g_h2);
    cudaGetSymbolAddress((void**)&off,   g_off);
    cudaGetSymbolAddress((void**)&maskb, g_mask);
    cudaGetSymbolAddress((void**)&w1p,   g_w1p);
    cudaGetSymbolAddress((void**)&mw1p,  g_mw1p);
    cudaGetSymbolAddress((void**)&w2p,   g_w2p);

    cudaFuncSetAttribute(k_gemm_bf16,
                         cudaFuncAttributeMaxDynamicSharedMemorySize, GEMM_SMEM);

    // 1. layout transform + weight prep (n-major packed bf16 pairs)
    k_transpose<<<dim3(4, 512, 8), dim3(32, 8)>>>(data);
    k_wprep<<<dim3(FIN / 64, FC / 32), dim3(32, 8)>>>(w1, mw1);
    k_w2prep<<<dim3(FC / 64, FC / 32), dim3(32, 8)>>>(w2);

    // 2. pool pass 1 -> xf bf16 [n][bin*256+c]
    k_pool<<<NROI * NBIN, 64>>>(rois, nullptr, nullptr, nullptr, xf, 1);

    // 3. G1 fused: xf @ w1 -> h1 (relu) | xf @ mw1 -> m1 (relu)   [bf16 TC]
    k_gemm_bf16<<<dim3(FC / 128, (NROI + 127) / 128, 2), 256, GEMM_SMEM>>>(
        xf, FIN, w1p, b1, h1, FC, mw1p, mb1, m1,
        NROI, FIN, 1);

    // 4. G2: h1 @ w2 -> h2 (relu)   [bf16 TC]
    k_gemm_bf16<<<dim3(FC / 128, (NROI + 127) / 128, 1), 256, GEMM_SMEM>>>(
        h1, FC, w2p, b2, h2, FC, nullptr, nullptr, nullptr,
        NROI, FC, 1);

    // 5. G3: h2 @ w3 -> offsets [2000,98]
    k_head<<<NROI / 8, 256>>>(h2, w3, b3, off, 98, 0);

    // 6. G4: m1 @ mw2 -> mask [2000,49] (sigmoid)
    k_head<<<NROI / 8, 256>>>(m1, mw2, mb2, maskb, 49, 2);

    // 7. pool pass 2 (offset + mask) -> d_out [N,C,7,7]
    k_pool<<<NROI * NBIN, 64>>>(rois, off, maskb, out, nullptr, 2);
}

// round 9
// speedup vs baseline: 1.0640x; 1.0640x over previous
#include <cuda_runtime.h>
#include <cuda_bf16.h>
#include <math.h>
#include <stdint.h>

#define OUTW 7
#define SPP 4
#define CCH 256
#define HH 128
#define WW 128
#define BB 4
#define NROI 2000
#define FIN (OUTW*OUTW*CCH)   /* 12544 */
#define FC 1024
#define NBIN (OUTW*OUTW)      /* 49 */
#define KP1 (FIN/2)           /* 6272 */
#define KP2 (FC/2)            /* 512 */

// ---------------- scratch (static device globals; no dynamic alloc) ----------
__device__ float          g_dataT[(size_t)BB*HH*WW*CCH];   // [B,H,W,C] 64 MB
__device__ __nv_bfloat16  g_xf[(size_t)NROI*FIN];          // pooled feats bf16
__device__ float          g_p2[(size_t)NROI*FIN];          // pass2 staging fp32
__device__ __nv_bfloat16  g_h1[(size_t)NROI*FC];
__device__ __nv_bfloat16  g_m1[(size_t)NROI*FC];
__device__ __nv_bfloat16  g_h2[(size_t)NROI*FC];
__device__ float          g_off[(size_t)NROI*2*NBIN];
__device__ float          g_mask[(size_t)NROI*NBIN];
__device__ uint32_t       g_w1p[(size_t)FC*KP1];           // [n][kp] bf16x2, permuted k
__device__ uint32_t       g_mw1p[(size_t)FC*KP1];
__device__ uint32_t       g_w2p[(size_t)FC*KP2];           // [n][kp]

// ---------------- helpers ------------------------------------------------------
__device__ __forceinline__ uint32_t packbf(float lo, float hi) {
    __nv_bfloat162 h = __floats2bfloat162_rn(lo, hi);
    return *(uint32_t*)&h;
}

__device__ __forceinline__ void mma_bf16(float* c, const uint32_t* a, const uint32_t* b) {
    asm volatile(
        "mma.sync.aligned.m16n8k16.row.col.f32.bf16.bf16.f32 "
        "{%0,%1,%2,%3}, {%4,%5,%6,%7}, {%8,%9}, {%0,%1,%2,%3};"
        : "+f"(c[0]), "+f"(c[1]), "+f"(c[2]), "+f"(c[3])
        : "r"(a[0]), "r"(a[1]), "r"(a[2]), "r"(a[3]), "r"(b[0]), "r"(b[1]));
}

__device__ __forceinline__ void ldsm_x4(uint32_t& r0, uint32_t& r1,
                                        uint32_t& r2, uint32_t& r3, uint32_t addr) {
    asm volatile("ldmatrix.sync.aligned.m8n8.x4.shared.b16 {%0,%1,%2,%3}, [%4];"
                 : "=r"(r0), "=r"(r1), "=r"(r2), "=r"(r3) : "r"(addr));
}

__device__ __forceinline__ void cp_async16(uint32_t dst, const void* src, bool pred) {
    int sz = pred ? 16 : 0;
    asm volatile("cp.async.cg.shared.global [%0], [%1], 16, %2;\n"
                 :: "r"(dst), "l"(src), "r"(sz));
}
__device__ __forceinline__ void cp_commit() {
    asm volatile("cp.async.commit_group;\n" ::: "memory");
}
template <int N>
__device__ __forceinline__ void cp_wait() {
    asm volatile("cp.async.wait_group %0;\n" :: "n"(N) : "memory");
}

// ---------------- transpose [B,C,H,W] -> [B,H,W,C] ---------------------------
__global__ void k_transpose(const float* __restrict__ data) {
    __shared__ float tile[32][33];
    int xt = blockIdx.x;
    int by = blockIdx.y;
    int ct = blockIdx.z;
    int b = by >> 7, y = by & 127;
    int x0 = xt * 32, c0 = ct * 32;
    int tx = threadIdx.x, ty = threadIdx.y;
#pragma unroll
    for (int i = 0; i < 4; i++) {
        int c = c0 + ty + 8 * i;
        tile[ty + 8 * i][tx] =
            data[(((size_t)b * CCH + c) * HH + y) * WW + x0 + tx];
    }
    __syncthreads();
#pragma unroll
    for (int i = 0; i < 4; i++) {
        int x = x0 + ty + 8 * i;
        g_dataT[(((size_t)b * HH + y) * WW + x) * CCH + c0 + tx] =
            tile[tx][ty + 8 * i];
    }
}

// ---------------- weight prep: w1/mw1 -> [n][kp] bf16x2, permuted k ----------
__global__ void k_wprep(const float* __restrict__ w1, const float* __restrict__ mw1) {
    __shared__ float t[64][33];
    int kk0 = blockIdx.x * 64;
    int n0 = blockIdx.y * 32;
    int tx = threadIdx.x, ty = threadIdx.y;   // 32 x 8

#pragma unroll
    for (int i = 0; i < 8; i++) {
        int gk = kk0 + ty + 8 * i;
        int c = gk & 255, bin = gk >> 8;
        t[ty + 8 * i][tx] = w1[(size_t)(c * NBIN + bin) * FC + n0 + tx];
    }
    __syncthreads();
#pragma unroll
    for (int i = 0; i < 4; i++) {
        int ny = ty + 8 * i;
        g_w1p[(size_t)(n0 + ny) * KP1 + (kk0 >> 1) + tx] =
            packbf(t[2 * tx][ny], t[2 * tx + 1][ny]);
    }
    __syncthreads();

#pragma unroll
    for (int i = 0; i < 8; i++) {
        int gk = kk0 + ty + 8 * i;
        int c = gk & 255, bin = gk >> 8;
        t[ty + 8 * i][tx] = mw1[(size_t)(c * NBIN + bin) * FC + n0 + tx];
    }
    __syncthreads();
#pragma unroll
    for (int i = 0; i < 4; i++) {
        int ny = ty + 8 * i;
        g_mw1p[(size_t)(n0 + ny) * KP1 + (kk0 >> 1) + tx] =
            packbf(t[2 * tx][ny], t[2 * tx + 1][ny]);
    }
}

__global__ void k_w2prep(const float* __restrict__ w2) {
    __shared__ float t[64][33];
    int kk0 = blockIdx.x * 64;
    int n0 = blockIdx.y * 32;
    int tx = threadIdx.x, ty = threadIdx.y;
#pragma unroll
    for (int i = 0; i < 8; i++)
        t[ty + 8 * i][tx] = w2[(size_t)(kk0 + ty + 8 * i) * FC + n0 + tx];
    __syncthreads();
#pragma unroll
    for (int i = 0; i < 4; i++) {
        int ny = ty + 8 * i;
        g_w2p[(size_t)(n0 + ny) * KP2 + (kk0 >> 1) + tx] =
            packbf(t[2 * tx][ny], t[2 * tx + 1][ny]);
    }
}

// ---------------- deform ROI pool: compact (offset,weight) list ---------------
// One (roi,bin) per 64-thread block; thread = 4 channels (float4).
// pass 1: outh = xf bf16 [n][bin*256+c].
// pass 2: outf = g_p2 fp32 [n][bin*256+c] (mask folded into norm).
__global__ void __launch_bounds__(64) k_pool(
        const float* __restrict__ rois,
        const float* __restrict__ offset,
        const float* __restrict__ mask,
        float* __restrict__ outf,
        __nv_bfloat16* __restrict__ outh,
        int pass) {
    int bidx = blockIdx.x;
    int n = bidx / NBIN;
    int bin = bidx % NBIN;
    int ph = bin / OUTW, pw = bin % OUTW;
    int tid = threadIdx.x;

    __shared__ float wcell[48];
    __shared__ int2  spk[40];
    __shared__ int   scnt;
    __shared__ float snorm;
    __shared__ int   sbase;
    __shared__ unsigned long long smask;

    if (tid < 48) wcell[tid] = 0.0f;
    __syncthreads();

    const float* r = rois + n * 5;
    if (tid < 16) {
        float sw = floorf(r[1] + 0.5f) * 0.0625f - 0.5f;
        float sh = floorf(r[2] + 0.5f) * 0.0625f - 0.5f;
        float ew = (floorf(r[3] + 0.5f) + 1.0f) * 0.0625f - 0.5f;
        float eh = (floorf(r[4] + 0.5f) + 1.0f) * 0.0625f - 0.5f;
        float rw = fmaxf(ew - sw, 0.1f);
        float rh = fmaxf(eh - sh, 0.1f);
        float bw = rw / 7.0f, bh = rh / 7.0f;
        float subw = bw / 4.0f, subh = bh / 4.0f;
        float ws0 = (float)pw * bw + sw;
        float hs0 = (float)ph * bh + sh;
        if (pass == 2) {
            ws0 += offset[(size_t)n * 98 + bin] * 0.1f * rw;
            hs0 += offset[(size_t)n * 98 + 49 + bin] * 0.1f * rh;
        }
        int ix = tid & 3, iy = tid >> 2;
        float w = ws0 + (float)ix * subw;
        float h = hs0 + (float)iy * subh;
        bool valid = (w >= -0.5f) && (w <= (float)WW - 0.5f) &&
                     (h >= -0.5f) && (h <= (float)HH - 0.5f);
        float wc = fminf(fmaxf(w, 0.0f), (float)(WW - 1));
        float hc = fminf(fmaxf(h, 0.0f), (float)(HH - 1));
        int x0 = (int)floorf(wc);
        int y0 = (int)floorf(hc);
        int x1 = min(x0 + 1, WW - 1);
        int y1 = min(y0 + 1, HH - 1);
        int gx = x0, gy = y0;
#pragma unroll
        for (int o = 8; o >= 1; o >>= 1) {
            gx = min(gx, __shfl_xor_sync(0xFFFFu, gx, o));
            gy = min(gy, __shfl_xor_sync(0xFFFFu, gy, o));
        }
        float dx = wc - (float)x0;
        float dy = hc - (float)y0;
        int c00 = ((y0 - gy) << 3) + (x0 - gx);
        int c01 = ((y0 - gy) << 3) + (x1 - gx);
        int c10 = ((y1 - gy) << 3) + (x0 - gx);
        int c11 = ((y1 - gy) << 3) + (x1 - gx);
        unsigned long long m = 0ull;
        float cnt = valid ? 1.0f : 0.0f;
        if (valid) {
            atomicAdd(&wcell[c00], (1.0f - dx) * (1.0f - dy));
            atomicAdd(&wcell[c01], dx * (1.0f - dy));
            atomicAdd(&wcell[c10], (1.0f - dx) * dy);
            atomicAdd(&wcell[c11], dx * dy);
            m = (1ull << c00) | (1ull << c01) | (1ull << c10) | (1ull << c11);
        }
#pragma unroll
        for (int o = 8; o >= 1; o >>= 1) {
            m |= __shfl_xor_sync(0xFFFFu, m, o);
            cnt += __shfl_xor_sync(0xFFFFu, cnt, o);
        }
        if (tid == 0) {
            smask = m;
            int b = (int)r[0];
            sbase = b * (HH * WW * 64) + (gy * WW + gx) * 64;  // float4 units
            float norm = (cnt > 0.0f) ? 1.0f / cnt : 0.0f;
            if (pass == 2) norm *= mask[(size_t)n * NBIN + bin];
            snorm = norm;
        }
    }
    __syncthreads();

    // warp 0: compact mask into (offsetWord, weight) pairs
    if (tid < 32) {
        unsigned long long m = smask;
        int c1 = tid;
        bool a1 = (m >> c1) & 1ull;
        unsigned b1 = __ballot_sync(0xFFFFFFFFu, a1);
        int cnt1 = __popc(b1);
        if (a1) {
            int idx = __popc(b1 & ((1u << tid) - 1u));
            int off = ((c1 >> 3) * WW + (c1 & 7)) * 64;
            spk[idx] = make_int2(off, __float_as_int(wcell[c1]));
        }
        int c2 = 32 + tid;
        bool a2 = (tid < 16) && ((m >> c2) & 1ull);
        unsigned b2 = __ballot_sync(0xFFFFFFFFu, a2);
        if (a2) {
            int idx = cnt1 + __popc(b2 & ((1u << tid) - 1u));
            int off = ((c2 >> 3) * WW + (c2 & 7)) * 64;
            spk[idx] = make_int2(off, __float_as_int(wcell[c2]));
        }
        if (tid == 0) scnt = cnt1 + __popc(b2);
    }
    __syncthreads();

    int cnt = scnt;
    float norm = snorm;
    const float4* base = (const float4*)g_dataT;
    int baseIdx = sbase + tid;

    float ax = 0.f, ay = 0.f, az = 0.f, aw = 0.f;
#pragma unroll 4
    for (int i = 0; i < cnt; i++) {
        int2 p = spk[i];
        float w = __int_as_float(p.y);
        float4 v = base[baseIdx + p.x];
        ax += w * v.x; ay += w * v.y; az += w * v.z; aw += w * v.w;
    }
    ax *= norm; ay *= norm; az *= norm; aw *= norm;

    if (pass == 2) {
        float4 v = make_float4(ax, ay, az, aw);
        *(float4*)(outf + (size_t)n * FIN + (size_t)bin * 256 + tid * 4) = v;
    } else {
        uint2 v = make_uint2(packbf(ax, ay), packbf(az, aw));
        *(uint2*)(outh + (size_t)n * FIN + (size_t)bin * 256 + tid * 4) = v;
    }
}

// ---------------- output transpose: [n][bin*256+c] -> [n][c*49+bin] ----------
#define OT_STRIDE 257
#define OT_SMEM (NBIN * OT_STRIDE * 4)
__global__ void __launch_bounds__(256) k_otrans(const float* __restrict__ in,
                                                float* __restrict__ out) {
    extern __shared__ float t[];
    int n = blockIdx.x;
    int tid = threadIdx.x;
    const float* src = in + (size_t)n * FIN;
    // load coalesced: idx = bin*256 + c
    for (int idx = tid; idx < FIN; idx += 256) {
        int bin = idx >> 8;
        int c = idx & 255;
        t[bin * OT_STRIDE + c] = src[idx];
    }
    __syncthreads();
    // store coalesced: j = c*49 + bin
    float* dst = out + (size_t)n * FIN;
    for (int j = tid; j < FIN; j += 256) {
        int c = j / NBIN;
        int bin = j - c * NBIN;
        dst[j] = t[bin * OT_STRIDE + c];
    }
}

// ---------------- bf16 tensor-core GEMM (4-stage cp.async + ldmatrix) ---------
#define LDA_S 20
#define LDB_S 20
#define STAGES 4
#define A_ST (128 * LDA_S)
#define B_ST (128 * LDB_S)
#define GEMM_SMEM ((STAGES * (A_ST + B_ST)) * 4)

__global__ void __launch_bounds__(256, 2) k_gemm_bf16(
    const __nv_bfloat16* __restrict__ A, int lda,
    const uint32_t* __restrict__ B,
    const float* __restrict__ bias,
    __nv_bfloat16* __restrict__ C, int ldc,
    const uint32_t* __restrict__ B2,
    const float* __restrict__ bias2,
    __nv_bfloat16* __restrict__ C2,
    int M, int K, int act) {
    if (blockIdx.z == 1) { B = B2; bias = bias2; C = C2; }
    int Kp = K >> 1;

    extern __shared__ uint32_t sm[];
    uint32_t* Asm = sm;
    uint32_t* Bsm = sm + STAGES * A_ST;

    int tid = threadIdx.x;
    int warp = tid >> 5, lane = tid & 31;
    int wm = warp >> 2;
    int wn = warp & 3;
    int bm = blockIdx.y * 128, bn = blockIdx.x * 128;

    int arow = tid >> 2;
    int akc  = (tid & 3) * 4;
    const __nv_bfloat16* Ap0 = A + (size_t)(bm + arow) * lda + akc * 2;
    const __nv_bfloat16* Ap1 = A + (size_t)(bm + arow + 64) * lda + akc * 2;
    bool am0 = (bm + arow) < M;
    bool am1 = (bm + arow + 64) < M;

    int brow = tid >> 2;
    int bkc  = (tid & 3) * 4;
    const uint32_t* Bq0 = B + (size_t)(bn + brow) * Kp + bkc;
    const uint32_t* Bq1 = B + (size_t)(bn + brow + 64) * Kp + bkc;

    uint32_t a_smem = (uint32_t)__cvta_generic_to_shared(Asm);
    uint32_t b_smem = (uint32_t)__cvta_generic_to_shared(Bsm);
    uint32_t da0 = a_smem + (uint32_t)(arow * LDA_S + akc) * 4;
    uint32_t da1 = a_smem + (uint32_t)((arow + 64) * LDA_S + akc) * 4;
    uint32_t db0 = b_smem + (uint32_t)(brow * LDB_S + bkc) * 4;
    uint32_t db1 = b_smem + (uint32_t)((brow + 64) * LDB_S + bkc) * 4;

    uint32_t a_lm = a_smem +
        (uint32_t)(((wm * 64 + (lane & 15)) * LDA_S) + ((lane >> 4) << 2)) * 4;
    uint32_t b_lm = b_smem +
        (uint32_t)(((wn * 32 + (lane & 7) + ((lane >> 4) << 3)) * LDB_S)
                   + (((lane >> 3) & 1) << 2)) * 4;

    float acc[4][4][4];
#pragma unroll
    for (int i = 0; i < 4; i++)
#pragma unroll
        for (int j = 0; j < 4; j++)
#pragma unroll
            for (int q = 0; q < 4; q++) acc[i][j][q] = 0.0f;

    int nt = K / 32;

#define LOAD_STAGE(kt, s)                                                      \
    {                                                                          \
        int ke = (kt) * 32;                                                    \
        int kp = (kt) * 16;                                                    \
        uint32_t ao = (uint32_t)(s) * A_ST * 4;                                \
        uint32_t bo = (uint32_t)(s) * B_ST * 4;                                \
        cp_async16(da0 + ao, Ap0 + ke, am0);                                   \
        cp_async16(da1 + ao, Ap1 + ke, am1);                                   \
        cp_async16(db0 + bo, Bq0 + kp, true);                                  \
        cp_async16(db1 + bo, Bq1 + kp, true);                                  \
        cp_commit();                                                           \
    }

    LOAD_STAGE(0, 0);
    LOAD_STAGE(1, 1);
    LOAD_STAGE(2, 2);

    for (int kt = 0; kt < nt; kt++) {
        cp_wait<STAGES - 2>();
        __syncthreads();
        if (kt + 3 < nt) {
            LOAD_STAGE(kt + 3, (kt + 3) & 3);
        } else {
            cp_commit();
        }

        int cur = kt & 3;
        uint32_t ab = a_lm + (uint32_t)cur * A_ST * 4;
        uint32_t bb = b_lm + (uint32_t)cur * B_ST * 4;

        uint32_t af[2][4][4], bf[2][4][2];
#pragma unroll
        for (int ko = 0; ko < 2; ko++) {
#pragma unroll
            for (int i = 0; i < 4; i++)
                ldsm_x4(af[ko][i][0], af[ko][i][1], af[ko][i][2], af[ko][i][3],
                        ab + (uint32_t)(i * 16 * LDA_S * 4 + ko * 32));
#pragma unroll
            for (int jj = 0; jj < 2; jj++)
                ldsm_x4(bf[ko][2 * jj][0], bf[ko][2 * jj][1],
                        bf[ko][2 * jj + 1][0], bf[ko][2 * jj + 1][1],
                        bb + (uint32_t)(jj * 16 * LDB_S * 4 + ko * 32));
        }
#pragma unroll
        for (int ko = 0; ko < 2; ko++)
#pragma unroll
            for (int i = 0; i < 4; i++)
#pragma unroll
                for (int j = 0; j < 4; j++)
                    mma_bf16(acc[i][j], af[ko][i], bf[ko][j]);
        __syncthreads();
    }
    cp_wait<0>();

    int g = lane >> 2, t = lane & 3;
#pragma unroll
    for (int i = 0; i < 4; i++) {
        int r0 = bm + wm * 64 + i * 16 + g;
        int r1 = r0 + 8;
#pragma unroll
        for (int j = 0; j < 4; j++) {
            int c0 = bn + wn * 32 + j * 8 + 2 * t;
            float bv0 = bias[c0], bv1 = bias[c0 + 1];
            float vv[4] = {acc[i][j][0] + bv0, acc[i][j][1] + bv1,
                           acc[i][j][2] + bv0, acc[i][j][3] + bv1};
#pragma unroll
            for (int q = 0; q < 4; q++) {
                if (act == 1) vv[q] = fmaxf(vv[q], 0.0f);
                else if (act == 2) vv[q] = 1.0f / (1.0f + expf(-vv[q]));
            }
            if (r0 < M)
                *(uint32_t*)(C + (size_t)r0 * ldc + c0) = packbf(vv[0], vv[1]);
            if (r1 < M)
                *(uint32_t*)(C + (size_t)r1 * ldc + c0) = packbf(vv[2], vv[3]);
        }
    }
#undef LOAD_STAGE
}

// ---------------- small-N head GEMM (A bf16, B/bias fp32) ---------------------
__global__ void __launch_bounds__(256) k_head(
        const __nv_bfloat16* __restrict__ A, const float* __restrict__ B,
        const float* __restrict__ bias, float* __restrict__ C,
        int N, int act) {
    __shared__ float Asm[8 * FC];
    int tid = threadIdx.x;
    int m0 = blockIdx.x * 8;
    const uint4* Af = (const uint4*)(A + (size_t)m0 * FC);
#pragma unroll
    for (int i = 0; i < 4; i++) {
        int idx = tid + 256 * i;
        uint4 u = Af[idx];
        float2 f0 = __bfloat1622float2(*(__nv_bfloat162*)&u.x);
        float2 f1 = __bfloat1622float2(*(__nv_bfloat162*)&u.y);
        float2 f2 = __bfloat1622float2(*(__nv_bfloat162*)&u.z);
        float2 f3 = __bfloat1622float2(*(__nv_bfloat162*)&u.w);
        float* d = Asm + idx * 8;
        d[0] = f0.x; d[1] = f0.y; d[2] = f1.x; d[3] = f1.y;
        d[4] = f2.x; d[5] = f2.y; d[6] = f3.x; d[7] = f3.y;
    }
    __syncthreads();

    int row = tid >> 5, lane = tid & 31;
    float acc[4] = {0.f, 0.f, 0.f, 0.f};
    const float* ar = Asm + row * FC;
    for (int k = 0; k < FC; k += 2) {
        float a0 = ar[k], a1 = ar[k + 1];
        const float* bk0 = B + (size_t)k * N;
        const float* bk1 = bk0 + N;
#pragma unroll
        for (int j = 0; j < 4; j++) {
            int col = lane + 32 * j;
            if (col < N) {
                acc[j] += a0 * bk0[col];
                acc[j] += a1 * bk1[col];
            }
        }
    }
#pragma unroll
    for (int j = 0; j < 4; j++) {
        int col = lane + 32 * j;
        if (col < N) {
            float v = acc[j] + bias[col];
            if (act == 1) v = fmaxf(v, 0.0f);
            else if (act == 2) v = 1.0f / (1.0f + expf(-v));
            C[(size_t)(m0 + row) * N + col] = v;
        }
    }
}

// ---------------- launch ------------------------------------------------------
extern "C" void kernel_launch(void* const* d_in, const int* in_sizes, int n_in,
                              void* d_out, int out_size) {
    const float* data = (const float*)d_in[0];
    const float* rois = (const float*)d_in[1];
    const float* w1   = (const float*)d_in[2];
    const float* b1   = (const float*)d_in[3];
    const float* w2   = (const float*)d_in[4];
    const float* b2   = (const float*)d_in[5];
    const float* w3   = (const float*)d_in[6];
    const float* b3   = (const float*)d_in[7];
    const float* mw1  = (const float*)d_in[8];
    const float* mb1  = (const float*)d_in[9];
    const float* mw2  = (const float*)d_in[10];
    const float* mb2  = (const float*)d_in[11];
    float* out = (float*)d_out;

    __nv_bfloat16 *xf, *h1, *m1, *h2;
    float *off, *maskb, *p2;
    uint32_t *w1p, *mw1p, *w2p;
    cudaGetSymbolAddress((void**)&xf,    g_xf);
    cudaGetSymbolAddress((void**)&h1,    g_h1);
    cudaGetSymbolAddress((void**)&m1,    g_m1);
    cudaGetSymbolAddress((void**)&h2,    g_h2);
    cudaGetSymbolAddress((void**)&off,   g_off);
    cudaGetSymbolAddress((void**)&maskb, g_mask);
    cudaGetSymbolAddress((void**)&p2,    g_p2);
    cudaGetSymbolAddress((void**)&w1p,   g_w1p);
    cudaGetSymbolAddress((void**)&mw1p,  g_mw1p);
    cudaGetSymbolAddress((void**)&w2p,   g_w2p);

    cudaFuncSetAttribute(k_gemm_bf16,
                         cudaFuncAttributeMaxDynamicSharedMemorySize, GEMM_SMEM);
    cudaFuncSetAttribute(k_otrans,
                         cudaFuncAttributeMaxDynamicSharedMemorySize, OT_SMEM);

    // 1. layout transform + weight prep (n-major packed bf16 pairs)
    k_transpose<<<dim3(4, 512, 8), dim3(32, 8)>>>(data);
    k_wprep<<<dim3(FIN / 64, FC / 32), dim3(32, 8)>>>(w1, mw1);
    k_w2prep<<<dim3(FC / 64, FC / 32), dim3(32, 8)>>>(w2);

    // 2. pool pass 1 -> xf bf16 [n][bin*256+c]
    k_pool<<<NROI * NBIN, 64>>>(rois, nullptr, nullptr, nullptr, xf, 1);

    // 3. G1 fused: xf @ w1 -> h1 (relu) | xf @ mw1 -> m1 (relu)   [bf16 TC]
    k_gemm_bf16<<<dim3(FC / 128, (NROI + 127) / 128, 2), 256, GEMM_SMEM>>>(
        xf, FIN, w1p, b1, h1, FC, mw1p, mb1, m1,
        NROI, FIN, 1);

    // 4. G2: h1 @ w2 -> h2 (relu)   [bf16 TC]
    k_gemm_bf16<<<dim3(FC / 128, (NROI + 127) / 128, 1), 256, GEMM_SMEM>>>(
        h1, FC, w2p, b2, h2, FC, nullptr, nullptr, nullptr,
        NROI, FC, 1);

    // 5. G3: h2 @ w3 -> offsets [2000,98]
    k_head<<<NROI / 8, 256>>>(h2, w3, b3, off, 98, 0);

    // 6. G4: m1 @ mw2 -> mask [2000,49] (sigmoid)
    k_head<<<NROI / 8, 256>>>(m1, mw2, mb2, maskb, 49, 2);

    // 7. pool pass 2 (offset + mask) -> staging [n][bin*256+c] coalesced
    k_pool<<<NROI * NBIN, 64>>>(rois, off, maskb, p2, nullptr, 2);

    // 8. transpose staging -> d_out [N,C,7,7]
    k_otrans<<<NROI, 256, OT_SMEM>>>(p2, out);
}

// round 10
// speedup vs baseline: 1.3714x; 1.2890x over previous
#include <cuda_runtime.h>
#include <cuda_bf16.h>
#include <math.h>
#include <stdint.h>

#define OUTW 7
#define SPP 4
#define CCH 256
#define HH 128
#define WW 128
#define BB 4
#define NROI 2000
#define FIN (OUTW*OUTW*CCH)   /* 12544 */
#define FC 1024
#define NBIN (OUTW*OUTW)      /* 49 */
#define KP1 (FIN/2)           /* 6272 */
#define KP2 (FC/2)            /* 512 */

// ---------------- scratch (static device globals; no dynamic alloc) ----------
__device__ float          g_dataT[(size_t)BB*HH*WW*CCH];   // [B,H,W,C] 64 MB
__device__ __nv_bfloat16  g_xf[(size_t)NROI*FIN];          // pooled feats bf16
__device__ float          g_p2[(size_t)NROI*FIN];          // pass2 staging fp32
__device__ __nv_bfloat16  g_h1[(size_t)NROI*FC];
__device__ __nv_bfloat16  g_m1[(size_t)NROI*FC];
__device__ __nv_bfloat16  g_h2[(size_t)NROI*FC];
__device__ float          g_off[(size_t)NROI*128];         // padded [n][128]
__device__ float          g_mask[(size_t)NROI*128];        // padded [n][128]
__device__ uint32_t       g_w1p[(size_t)FC*KP1];           // [n][kp] bf16x2, permuted k
__device__ uint32_t       g_mw1p[(size_t)FC*KP1];
__device__ uint32_t       g_w2p[(size_t)FC*KP2];           // [n][kp]
__device__ uint32_t       g_w3p[(size_t)128*KP2];          // heads n-major padded
__device__ uint32_t       g_mw2p[(size_t)128*KP2];
__device__ float          g_b3p[128];
__device__ float          g_mb2p[128];

// ---------------- helpers ------------------------------------------------------
__device__ __forceinline__ uint32_t packbf(float lo, float hi) {
    __nv_bfloat162 h = __floats2bfloat162_rn(lo, hi);
    return *(uint32_t*)&h;
}

__device__ __forceinline__ void mma_bf16(float* c, const uint32_t* a, const uint32_t* b) {
    asm volatile(
        "mma.sync.aligned.m16n8k16.row.col.f32.bf16.bf16.f32 "
        "{%0,%1,%2,%3}, {%4,%5,%6,%7}, {%8,%9}, {%0,%1,%2,%3};"
        : "+f"(c[0]), "+f"(c[1]), "+f"(c[2]), "+f"(c[3])
        : "r"(a[0]), "r"(a[1]), "r"(a[2]), "r"(a[3]), "r"(b[0]), "r"(b[1]));
}

__device__ __forceinline__ void ldsm_x4(uint32_t& r0, uint32_t& r1,
                                        uint32_t& r2, uint32_t& r3, uint32_t addr) {
    asm volatile("ldmatrix.sync.aligned.m8n8.x4.shared.b16 {%0,%1,%2,%3}, [%4];"
                 : "=r"(r0), "=r"(r1), "=r"(r2), "=r"(r3) : "r"(addr));
}

__device__ __forceinline__ void cp_async16(uint32_t dst, const void* src, bool pred) {
    int sz = pred ? 16 : 0;
    asm volatile("cp.async.cg.shared.global [%0], [%1], 16, %2;\n"
                 :: "r"(dst), "l"(src), "r"(sz));
}
__device__ __forceinline__ void cp_commit() {
    asm volatile("cp.async.commit_group;\n" ::: "memory");
}
template <int N>
__device__ __forceinline__ void cp_wait() {
    asm volatile("cp.async.wait_group %0;\n" :: "n"(N) : "memory");
}

// ---------------- transpose [B,C,H,W] -> [B,H,W,C] ---------------------------
__global__ void k_transpose(const float* __restrict__ data) {
    __shared__ float tile[32][33];
    int xt = blockIdx.x;
    int by = blockIdx.y;
    int ct = blockIdx.z;
    int b = by >> 7, y = by & 127;
    int x0 = xt * 32, c0 = ct * 32;
    int tx = threadIdx.x, ty = threadIdx.y;
#pragma unroll
    for (int i = 0; i < 4; i++) {
        int c = c0 + ty + 8 * i;
        tile[ty + 8 * i][tx] =
            data[(((size_t)b * CCH + c) * HH + y) * WW + x0 + tx];
    }
    __syncthreads();
#pragma unroll
    for (int i = 0; i < 4; i++) {
        int x = x0 + ty + 8 * i;
        g_dataT[(((size_t)b * HH + y) * WW + x) * CCH + c0 + tx] =
            tile[tx][ty + 8 * i];
    }
}

// ---------------- weight prep: w1/mw1 -> [n][kp] bf16x2, permuted k ----------
__global__ void k_wprep(const float* __restrict__ w1, const float* __restrict__ mw1) {
    __shared__ float t[64][33];
    int kk0 = blockIdx.x * 64;
    int n0 = blockIdx.y * 32;
    int tx = threadIdx.x, ty = threadIdx.y;   // 32 x 8

#pragma unroll
    for (int i = 0; i < 8; i++) {
        int gk = kk0 + ty + 8 * i;
        int c = gk & 255, bin = gk >> 8;
        t[ty + 8 * i][tx] = w1[(size_t)(c * NBIN + bin) * FC + n0 + tx];
    }
    __syncthreads();
#pragma unroll
    for (int i = 0; i < 4; i++) {
        int ny = ty + 8 * i;
        g_w1p[(size_t)(n0 + ny) * KP1 + (kk0 >> 1) + tx] =
            packbf(t[2 * tx][ny], t[2 * tx + 1][ny]);
    }
    __syncthreads();

#pragma unroll
    for (int i = 0; i < 8; i++) {
        int gk = kk0 + ty + 8 * i;
        int c = gk & 255, bin = gk >> 8;
        t[ty + 8 * i][tx] = mw1[(size_t)(c * NBIN + bin) * FC + n0 + tx];
    }
    __syncthreads();
#pragma unroll
    for (int i = 0; i < 4; i++) {
        int ny = ty + 8 * i;
        g_mw1p[(size_t)(n0 + ny) * KP1 + (kk0 >> 1) + tx] =
            packbf(t[2 * tx][ny], t[2 * tx + 1][ny]);
    }
}

__global__ void k_w2prep(const float* __restrict__ w2) {
    __shared__ float t[64][33];
    int kk0 = blockIdx.x * 64;
    int n0 = blockIdx.y * 32;
    int tx = threadIdx.x, ty = threadIdx.y;
#pragma unroll
    for (int i = 0; i < 8; i++)
        t[ty + 8 * i][tx] = w2[(size_t)(kk0 + ty + 8 * i) * FC + n0 + tx];
    __syncthreads();
#pragma unroll
    for (int i = 0; i < 4; i++) {
        int ny = ty + 8 * i;
        g_w2p[(size_t)(n0 + ny) * KP2 + (kk0 >> 1) + tx] =
            packbf(t[2 * tx][ny], t[2 * tx + 1][ny]);
    }
}

// ---------------- head weight prep: w3 [1024][98], mw2 [1024][49] -> n-major --
__global__ void k_hprep(const float* __restrict__ w3, const float* __restrict__ b3,
                        const float* __restrict__ mw2, const float* __restrict__ mb2) {
    int n = blockIdx.x;        // 0..127
    int kp = threadIdx.x;      // 0..255
#pragma unroll
    for (int q = 0; q < 2; q++) {
        int k2 = kp + q * 256;
        float a = 0.f, b = 0.f, c = 0.f, d = 0.f;
        if (n < 98)  { a = w3[(size_t)(2 * k2) * 98 + n];
                       b = w3[(size_t)(2 * k2 + 1) * 98 + n]; }
        if (n < 49)  { c = mw2[(size_t)(2 * k2) * 49 + n];
                       d = mw2[(size_t)(2 * k2 + 1) * 49 + n]; }
        g_w3p[(size_t)n * KP2 + k2]  = packbf(a, b);
        g_mw2p[(size_t)n * KP2 + k2] = packbf(c, d);
    }
    if (kp == 0) {
        g_b3p[n]  = (n < 98) ? b3[n]  : 0.f;
        g_mb2p[n] = (n < 49) ? mb2[n] : 0.f;
    }
}

// ---------------- deform ROI pool: compact (offset,weight) list ---------------
// pass 1: outh = xf bf16 [n][bin*256+c].
// pass 2: outf = g_p2 fp32 [n][bin*256+c] (mask folded into norm).
// offset/mask use padded [n][128] layouts.
__global__ void __launch_bounds__(64) k_pool(
        const float* __restrict__ rois,
        const float* __restrict__ offset,
        const float* __restrict__ mask,
        float* __restrict__ outf,
        __nv_bfloat16* __restrict__ outh,
        int pass) {
    int bidx = blockIdx.x;
    int n = bidx / NBIN;
    int bin = bidx % NBIN;
    int ph = bin / OUTW, pw = bin % OUTW;
    int tid = threadIdx.x;

    __shared__ float wcell[48];
    __shared__ int2  spk[40];
    __shared__ int   scnt;
    __shared__ float snorm;
    __shared__ int   sbase;
    __shared__ unsigned long long smask;

    if (tid < 48) wcell[tid] = 0.0f;
    __syncthreads();

    const float* r = rois + n * 5;
    if (tid < 16) {
        float sw = floorf(r[1] + 0.5f) * 0.0625f - 0.5f;
        float sh = floorf(r[2] + 0.5f) * 0.0625f - 0.5f;
        float ew = (floorf(r[3] + 0.5f) + 1.0f) * 0.0625f - 0.5f;
        float eh = (floorf(r[4] + 0.5f) + 1.0f) * 0.0625f - 0.5f;
        float rw = fmaxf(ew - sw, 0.1f);
        float rh = fmaxf(eh - sh, 0.1f);
        float bw = rw / 7.0f, bh = rh / 7.0f;
        float subw = bw / 4.0f, subh = bh / 4.0f;
        float ws0 = (float)pw * bw + sw;
        float hs0 = (float)ph * bh + sh;
        if (pass == 2) {
            ws0 += offset[(size_t)n * 128 + bin] * 0.1f * rw;
            hs0 += offset[(size_t)n * 128 + 49 + bin] * 0.1f * rh;
        }
        int ix = tid & 3, iy = tid >> 2;
        float w = ws0 + (float)ix * subw;
        float h = hs0 + (float)iy * subh;
        bool valid = (w >= -0.5f) && (w <= (float)WW - 0.5f) &&
                     (h >= -0.5f) && (h <= (float)HH - 0.5f);
        float wc = fminf(fmaxf(w, 0.0f), (float)(WW - 1));
        float hc = fminf(fmaxf(h, 0.0f), (float)(HH - 1));
        int x0 = (int)floorf(wc);
        int y0 = (int)floorf(hc);
        int x1 = min(x0 + 1, WW - 1);
        int y1 = min(y0 + 1, HH - 1);
        int gx = x0, gy = y0;
#pragma unroll
        for (int o = 8; o >= 1; o >>= 1) {
            gx = min(gx, __shfl_xor_sync(0xFFFFu, gx, o));
            gy = min(gy, __shfl_xor_sync(0xFFFFu, gy, o));
        }
        float dx = wc - (float)x0;
        float dy = hc - (float)y0;
        int c00 = ((y0 - gy) << 3) + (x0 - gx);
        int c01 = ((y0 - gy) << 3) + (x1 - gx);
        int c10 = ((y1 - gy) << 3) + (x0 - gx);
        int c11 = ((y1 - gy) << 3) + (x1 - gx);
        unsigned long long m = 0ull;
        float cnt = valid ? 1.0f : 0.0f;
        if (valid) {
            atomicAdd(&wcell[c00], (1.0f - dx) * (1.0f - dy));
            atomicAdd(&wcell[c01], dx * (1.0f - dy));
            atomicAdd(&wcell[c10], (1.0f - dx) * dy);
            atomicAdd(&wcell[c11], dx * dy);
            m = (1ull << c00) | (1ull << c01) | (1ull << c10) | (1ull << c11);
        }
#pragma unroll
        for (int o = 8; o >= 1; o >>= 1) {
            m |= __shfl_xor_sync(0xFFFFu, m, o);
            cnt += __shfl_xor_sync(0xFFFFu, cnt, o);
        }
        if (tid == 0) {
            smask = m;
            int b = (int)r[0];
            sbase = b * (HH * WW * 64) + (gy * WW + gx) * 64;  // float4 units
            float norm = (cnt > 0.0f) ? 1.0f / cnt : 0.0f;
            if (pass == 2) norm *= mask[(size_t)n * 128 + bin];
            snorm = norm;
        }
    }
    __syncthreads();

    if (tid < 32) {
        unsigned long long m = smask;
        int c1 = tid;
        bool a1 = (m >> c1) & 1ull;
        unsigned b1 = __ballot_sync(0xFFFFFFFFu, a1);
        int cnt1 = __popc(b1);
        if (a1) {
            int idx = __popc(b1 & ((1u << tid) - 1u));
            int off = ((c1 >> 3) * WW + (c1 & 7)) * 64;
            spk[idx] = make_int2(off, __float_as_int(wcell[c1]));
        }
        int c2 = 32 + tid;
        bool a2 = (tid < 16) && ((m >> c2) & 1ull);
        unsigned b2 = __ballot_sync(0xFFFFFFFFu, a2);
        if (a2) {
            int idx = cnt1 + __popc(b2 & ((1u << tid) - 1u));
            int off = ((c2 >> 3) * WW + (c2 & 7)) * 64;
            spk[idx] = make_int2(off, __float_as_int(wcell[c2]));
        }
        if (tid == 0) scnt = cnt1 + __popc(b2);
    }
    __syncthreads();

    int cnt = scnt;
    float norm = snorm;
    const float4* base = (const float4*)g_dataT;
    int baseIdx = sbase + tid;

    float ax = 0.f, ay = 0.f, az = 0.f, aw = 0.f;
#pragma unroll 4
    for (int i = 0; i < cnt; i++) {
        int2 p = spk[i];
        float w = __int_as_float(p.y);
        float4 v = base[baseIdx + p.x];
        ax += w * v.x; ay += w * v.y; az += w * v.z; aw += w * v.w;
    }
    ax *= norm; ay *= norm; az *= norm; aw *= norm;

    if (pass == 2) {
        float4 v = make_float4(ax, ay, az, aw);
        *(float4*)(outf + (size_t)n * FIN + (size_t)bin * 256 + tid * 4) = v;
    } else {
        uint2 v = make_uint2(packbf(ax, ay), packbf(az, aw));
        *(uint2*)(outh + (size_t)n * FIN + (size_t)bin * 256 + tid * 4) = v;
    }
}

// ---------------- output transpose: [n][bin*256+c] -> [n][c*49+bin] ----------
#define OT_STRIDE 257
#define OT_SMEM (NBIN * OT_STRIDE * 4)
__global__ void __launch_bounds__(256) k_otrans(const float* __restrict__ in,
                                                float* __restrict__ out) {
    extern __shared__ float t[];
    int n = blockIdx.x;
    int tid = threadIdx.x;
    const float* src = in + (size_t)n * FIN;
    for (int idx = tid; idx < FIN; idx += 256) {
        int bin = idx >> 8;
        int c = idx & 255;
        t[bin * OT_STRIDE + c] = src[idx];
    }
    __syncthreads();
    float* dst = out + (size_t)n * FIN;
    for (int j = tid; j < FIN; j += 256) {
        int c = j / NBIN;
        int bin = j - c * NBIN;
        dst[j] = t[bin * OT_STRIDE + c];
    }
}

// ---------------- bf16 tensor-core GEMM (4-stage cp.async + ldmatrix) ---------
// A [M,K] bf16 row-major (lda elems). B n-major u32 [N][K/2].
// Output: bf16 C (ldc) or fp32 Cf (ldc). act: 0 none, 1 relu, 2 sigmoid,
// 3 = per-z (z0: none, z1: sigmoid). z==1 uses A2/B2/bias2/C2/Cf2.
#define LDA_S 20
#define LDB_S 20
#define STAGES 4
#define A_ST (128 * LDA_S)
#define B_ST (128 * LDB_S)
#define GEMM_SMEM ((STAGES * (A_ST + B_ST)) * 4)

__global__ void __launch_bounds__(256, 2) k_gemm_bf16(
    const __nv_bfloat16* __restrict__ A, int lda,
    const uint32_t* __restrict__ B,
    const float* __restrict__ bias,
    __nv_bfloat16* __restrict__ C, int ldc,
    float* __restrict__ Cf,
    const __nv_bfloat16* __restrict__ A2,
    const uint32_t* __restrict__ B2,
    const float* __restrict__ bias2,
    __nv_bfloat16* __restrict__ C2,
    float* __restrict__ Cf2,
    int M, int K, int act) {
    if (blockIdx.z == 1) {
        B = B2; bias = bias2; C = C2; Cf = Cf2;
        if (A2) A = A2;
    }
    int actv = act;
    if (act == 3) actv = (blockIdx.z == 1) ? 2 : 0;
    int Kp = K >> 1;

    extern __shared__ uint32_t sm[];
    uint32_t* Asm = sm;
    uint32_t* Bsm = sm + STAGES * A_ST;

    int tid = threadIdx.x;
    int warp = tid >> 5, lane = tid & 31;
    int wm = warp >> 2;
    int wn = warp & 3;
    int bm = blockIdx.y * 128, bn = blockIdx.x * 128;

    int arow = tid >> 2;
    int akc  = (tid & 3) * 4;
    const __nv_bfloat16* Ap0 = A + (size_t)(bm + arow) * lda + akc * 2;
    const __nv_bfloat16* Ap1 = A + (size_t)(bm + arow + 64) * lda + akc * 2;
    bool am0 = (bm + arow) < M;
    bool am1 = (bm + arow + 64) < M;

    int brow = tid >> 2;
    int bkc  = (tid & 3) * 4;
    const uint32_t* Bq0 = B + (size_t)(bn + brow) * Kp + bkc;
    const uint32_t* Bq1 = B + (size_t)(bn + brow + 64) * Kp + bkc;

    uint32_t a_smem = (uint32_t)__cvta_generic_to_shared(Asm);
    uint32_t b_smem = (uint32_t)__cvta_generic_to_shared(Bsm);
    uint32_t da0 = a_smem + (uint32_t)(arow * LDA_S + akc) * 4;
    uint32_t da1 = a_smem + (uint32_t)((arow + 64) * LDA_S + akc) * 4;
    uint32_t db0 = b_smem + (uint32_t)(brow * LDB_S + bkc) * 4;
    uint32_t db1 = b_smem + (uint32_t)((brow + 64) * LDB_S + bkc) * 4;

    uint32_t a_lm = a_smem +
        (uint32_t)(((wm * 64 + (lane & 15)) * LDA_S) + ((lane >> 4) << 2)) * 4;
    uint32_t b_lm = b_smem +
        (uint32_t)(((wn * 32 + (lane & 7) + ((lane >> 4) << 3)) * LDB_S)
                   + (((lane >> 3) & 1) << 2)) * 4;

    float acc[4][4][4];
#pragma unroll
    for (int i = 0; i < 4; i++)
#pragma unroll
        for (int j = 0; j < 4; j++)
#pragma unroll
            for (int q = 0; q < 4; q++) acc[i][j][q] = 0.0f;

    int nt = K / 32;

#define LOAD_STAGE(kt, s)                                                      \
    {                                                                          \
        int ke = (kt) * 32;                                                    \
        int kp = (kt) * 16;                                                    \
        uint32_t ao = (uint32_t)(s) * A_ST * 4;                                \
        uint32_t bo = (uint32_t)(s) * B_ST * 4;                                \
        cp_async16(da0 + ao, Ap0 + ke, am0);                                   \
        cp_async16(da1 + ao, Ap1 + ke, am1);                                   \
        cp_async16(db0 + bo, Bq0 + kp, true);                                  \
        cp_async16(db1 + bo, Bq1 + kp, true);                                  \
        cp_commit();                                                           \
    }

    LOAD_STAGE(0, 0);
    LOAD_STAGE(1, 1);
    LOAD_STAGE(2, 2);

    for (int kt = 0; kt < nt; kt++) {
        cp_wait<STAGES - 2>();
        __syncthreads();        // single barrier per iteration (see hazard proof)
        if (kt + 3 < nt) {
            LOAD_STAGE(kt + 3, (kt + 3) & 3);
        } else {
            cp_commit();
        }

        int cur = kt & 3;
        uint32_t ab = a_lm + (uint32_t)cur * A_ST * 4;
        uint32_t bb = b_lm + (uint32_t)cur * B_ST * 4;

        uint32_t af[2][4][4], bf[2][4][2];
#pragma unroll
        for (int ko = 0; ko < 2; ko++) {
#pragma unroll
            for (int i = 0; i < 4; i++)
                ldsm_x4(af[ko][i][0], af[ko][i][1], af[ko][i][2], af[ko][i][3],
                        ab + (uint32_t)(i * 16 * LDA_S * 4 + ko * 32));
#pragma unroll
            for (int jj = 0; jj < 2; jj++)
                ldsm_x4(bf[ko][2 * jj][0], bf[ko][2 * jj][1],
                        bf[ko][2 * jj + 1][0], bf[ko][2 * jj + 1][1],
                        bb + (uint32_t)(jj * 16 * LDB_S * 4 + ko * 32));
        }
#pragma unroll
        for (int ko = 0; ko < 2; ko++)
#pragma unroll
            for (int i = 0; i < 4; i++)
#pragma unroll
                for (int j = 0; j < 4; j++)
                    mma_bf16(acc[i][j], af[ko][i], bf[ko][j]);
    }
    cp_wait<0>();

    int g = lane >> 2, t = lane & 3;
#pragma unroll
    for (int i = 0; i < 4; i++) {
        int r0 = bm + wm * 64 + i * 16 + g;
        int r1 = r0 + 8;
#pragma unroll
        for (int j = 0; j < 4; j++) {
            int c0 = bn + wn * 32 + j * 8 + 2 * t;
            float bv0 = bias[c0], bv1 = bias[c0 + 1];
            float vv[4] = {acc[i][j][0] + bv0, acc[i][j][1] + bv1,
                           acc[i][j][2] + bv0, acc[i][j][3] + bv1};
#pragma unroll
            for (int q = 0; q < 4; q++) {
                if (actv == 1) vv[q] = fmaxf(vv[q], 0.0f);
                else if (actv == 2) vv[q] = 1.0f / (1.0f + expf(-vv[q]));
            }
            if (Cf) {
                if (r0 < M) {
                    Cf[(size_t)r0 * ldc + c0]     = vv[0];
                    Cf[(size_t)r0 * ldc + c0 + 1] = vv[1];
                }
                if (r1 < M) {
                    Cf[(size_t)r1 * ldc + c0]     = vv[2];
                    Cf[(size_t)r1 * ldc + c0 + 1] = vv[3];
                }
            } else {
                if (r0 < M)
                    *(uint32_t*)(C + (size_t)r0 * ldc + c0) = packbf(vv[0], vv[1]);
                if (r1 < M)
                    *(uint32_t*)(C + (size_t)r1 * ldc + c0) = packbf(vv[2], vv[3]);
            }
        }
    }
#undef LOAD_STAGE
}

// ---------------- launch ------------------------------------------------------
extern "C" void kernel_launch(void* const* d_in, const int* in_sizes, int n_in,
                              void* d_out, int out_size) {
    const float* data = (const float*)d_in[0];
    const float* rois = (const float*)d_in[1];
    const float* w1   = (const float*)d_in[2];
    const float* b1   = (const float*)d_in[3];
    const float* w2   = (const float*)d_in[4];
    const float* b2   = (const float*)d_in[5];
    const float* w3   = (const float*)d_in[6];
    const float* b3   = (const float*)d_in[7];
    const float* mw1  = (const float*)d_in[8];
    const float* mb1  = (const float*)d_in[9];
    const float* mw2  = (const float*)d_in[10];
    const float* mb2  = (const float*)d_in[11];
    float* out = (float*)d_out;

    __nv_bfloat16 *xf, *h1, *m1, *h2;
    float *off, *maskb, *p2, *b3p, *mb2p;
    uint32_t *w1p, *mw1p, *w2p, *w3p, *mw2p;
    cudaGetSymbolAddress((void**)&xf,    g_xf);
    cudaGetSymbolAddress((void**)&h1,    g_h1);
    cudaGetSymbolAddress((void**)&m1,    g_m1);
    cudaGetSymbolAddress((void**)&h2,    g_h2);
    cudaGetSymbolAddress((void**)&off,   g_off);
    cudaGetSymbolAddress((void**)&maskb, g_mask);
    cudaGetSymbolAddress((void**)&p2,    g_p2);
    cudaGetSymbolAddress((void**)&w1p,   g_w1p);
    cudaGetSymbolAddress((void**)&mw1p,  g_mw1p);
    cudaGetSymbolAddress((void**)&w2p,   g_w2p);
    cudaGetSymbolAddress((void**)&w3p,   g_w3p);
    cudaGetSymbolAddress((void**)&mw2p,  g_mw2p);
    cudaGetSymbolAddress((void**)&b3p,   g_b3p);
    cudaGetSymbolAddress((void**)&mb2p,  g_mb2p);

    cudaFuncSetAttribute(k_gemm_bf16,
                         cudaFuncAttributeMaxDynamicSharedMemorySize, GEMM_SMEM);
    cudaFuncSetAttribute(k_otrans,
                         cudaFuncAttributeMaxDynamicSharedMemorySize, OT_SMEM);

    // 1. layout transform + weight prep (n-major packed bf16 pairs)
    k_transpose<<<dim3(4, 512, 8), dim3(32, 8)>>>(data);
    k_wprep<<<dim3(FIN / 64, FC / 32), dim3(32, 8)>>>(w1, mw1);
    k_w2prep<<<dim3(FC / 64, FC / 32), dim3(32, 8)>>>(w2);
    k_hprep<<<128, 256>>>(w3, b3, mw2, mb2);

    // 2. pool pass 1 -> xf bf16 [n][bin*256+c]
    k_pool<<<NROI * NBIN, 64>>>(rois, nullptr, nullptr, nullptr, xf, 1);

    // 3. G1 fused: xf @ w1 -> h1 (relu) | xf @ mw1 -> m1 (relu)   [bf16 TC]
    k_gemm_bf16<<<dim3(FC / 128, (NROI + 127) / 128, 2), 256, GEMM_SMEM>>>(
        xf, FIN, w1p, b1, h1, FC, nullptr,
        nullptr, mw1p, mb1, m1, nullptr,
        NROI, FIN, 1);

    // 4. G2: h1 @ w2 -> h2 (relu)   [bf16 TC]
    k_gemm_bf16<<<dim3(FC / 128, (NROI + 127) / 128, 1), 256, GEMM_SMEM>>>(
        h1, FC, w2p, b2, h2, FC, nullptr,
        nullptr, nullptr, nullptr, nullptr, nullptr,
        NROI, FC, 1);

    // 5+6. fused heads: z0: h2 @ w3 -> off fp32 [n][128] (linear)
    //                   z1: m1 @ mw2 -> mask fp32 [n][128] (sigmoid)
    k_gemm_bf16<<<dim3(1, (NROI + 127) / 128, 2), 256, GEMM_SMEM>>>(
        h2, FC, w3p, b3p, nullptr, 128, off,
        m1, mw2p, mb2p, nullptr, maskb,
        NROI, FC, 3);

    // 7. pool pass 2 (offset + mask) -> staging [n][bin*256+c] coalesced
    k_pool<<<NROI * NBIN, 64>>>(rois, off, maskb, p2, nullptr, 2);

    // 8. transpose staging -> d_out [N,C,7,7]
    k_otrans<<<NROI, 256, OT_SMEM>>>(p2, out);
}